// round 12
// baseline (speedup 1.0000x reference)
#include <cuda_runtime.h>
#include <cuda_fp16.h>
#include <cstdint>
#include <math.h>

#define TGT 2048
#define BSZ 4
#define EMB 1024
#define NH  16
#define HD  64
#define MROWS (TGT * BSZ)          // 8192
#define BH (BSZ * NH)              // 64
#define SKH 72                     // padded half-stride for 64-wide fp16 tiles
#define TT ((size_t)TGT * TGT)

// scratch (device globals: allocation-free per harness rules). uint4 for alignment.
__device__ uint4 g_qh[(size_t)MROWS * EMB / 8];      // fp16 q   [t][b][e]
__device__ uint4 g_kh[(size_t)MROWS * EMB / 8];      // fp16 k   [t][b][e]
__device__ uint4 g_vh[(size_t)MROWS * EMB / 8];      // fp16 v   [t][b][e]
__device__ uint4 g_vt[(size_t)MROWS * EMB / 8];      // fp16 v^T [b*EMB+e][t]
__device__ uint4 g_ctxh[(size_t)MROWS * EMB / 8];    // fp16 ctx [t][b][e]
__device__ float g_linv[(size_t)BH * TGT];           // 1/rowsum(exp S)
__device__ uint4 g_e[BH * TT / 8];                   // E=exp(S) fp16, 536 MB

// ---------------------------------------------------------------------------
// helpers
// ---------------------------------------------------------------------------
__device__ __forceinline__ unsigned f2h2(float a, float b) {
    __half2 h = __floats2half2_rn(a, b);
    return *reinterpret_cast<unsigned*>(&h);
}

__device__ __forceinline__ void mma16(float* c,
                                      unsigned a0, unsigned a1, unsigned a2, unsigned a3,
                                      unsigned b0, unsigned b1) {
    asm volatile(
        "mma.sync.aligned.m16n8k16.row.col.f32.f16.f16.f32 "
        "{%0,%1,%2,%3}, {%4,%5,%6,%7}, {%8,%9}, {%0,%1,%2,%3};\n"
        : "+f"(c[0]), "+f"(c[1]), "+f"(c[2]), "+f"(c[3])
        : "r"(a0), "r"(a1), "r"(a2), "r"(a3), "r"(b0), "r"(b1));
}

__device__ __forceinline__ void cp16(void* dst, const void* src) {
    uint32_t d = (uint32_t)__cvta_generic_to_shared(dst);
    asm volatile("cp.async.cg.shared.global [%0], [%1], 16;\n" :: "r"(d), "l"(src));
}
#define CP_COMMIT() asm volatile("cp.async.commit_group;\n" ::: "memory")
#define CP_WAIT0()  asm volatile("cp.async.wait_group 0;\n" ::: "memory")

// ---------------------------------------------------------------------------
// Shared GEMM smem layout (double-buffered fp16 tiles)
// ---------------------------------------------------------------------------
struct GemmSmem {
    unsigned short As[2][128][SKH];
    unsigned short Bs[2][128][SKH];
};
#define GEMM_SMEM ((int)sizeof(GemmSmem))

// ---------------------------------------------------------------------------
// Merged QKV projection: one launch, blockIdx.z in {0,1,2} = {Q,K,V}.
// C_z = (x @ W_z^T + bias_z) * scale_z, fp16 output.
// BM=BN=128, BK=64. 256 threads = 8 warps (2m x 4n), warp tile 64x32.
// ---------------------------------------------------------------------------
__global__ __launch_bounds__(256)
void gemm_qkv(const float* __restrict__ x,
              const float* __restrict__ wq, const float* __restrict__ bq,
              const float* __restrict__ wk, const float* __restrict__ bk,
              const float* __restrict__ wv, const float* __restrict__ bv,
              __half* __restrict__ qh, __half* __restrict__ kh,
              __half* __restrict__ vh)
{
    extern __shared__ char smem_raw[];
    GemmSmem& sm = *reinterpret_cast<GemmSmem*>(smem_raw);
    const int K = EMB, N = EMB;
    int tid = threadIdx.x, lane = tid & 31, warp = tid >> 5;
    int g = lane >> 2, t = lane & 3;
    int wm = warp >> 2, wn = warp & 3;
    int m0 = blockIdx.y * 128, n0 = blockIdx.x * 128;
    int zi = blockIdx.z;

    const float* W  = (zi == 0) ? wq : (zi == 1) ? wk : wv;
    const float* bi = (zi == 0) ? bq : (zi == 1) ? bk : bv;
    __half* C       = (zi == 0) ? qh : (zi == 1) ? kh : vh;
    const float scale = (zi == 0) ? 0.125f : 1.0f;

    const float* Ab = x + (size_t)m0 * K;
    const float* Wb = W + (size_t)n0 * K;
    float acc[4][4][4] = {};

    // stage k-tile 0
    #pragma unroll
    for (int i = 0; i < 8; i++) {
        int li = tid + i * 256;
        int m = li >> 4, c4 = li & 15;
        float4 va = *reinterpret_cast<const float4*>(Ab + (size_t)m * K + c4 * 4);
        *reinterpret_cast<uint2*>(&sm.As[0][m][c4 * 4]) =
            make_uint2(f2h2(va.x, va.y), f2h2(va.z, va.w));
        float4 vb = *reinterpret_cast<const float4*>(Wb + (size_t)m * K + c4 * 4);
        *reinterpret_cast<uint2*>(&sm.Bs[0][m][c4 * 4]) =
            make_uint2(f2h2(vb.x, vb.y), f2h2(vb.z, vb.w));
    }
    __syncthreads();

    const int NKT = K / 64;   // 16
    for (int kt = 0; kt < NKT; kt++) {
        int buf = kt & 1;
        uint2 ar[8], br[8];
        if (kt + 1 < NKT) {
            int ko = (kt + 1) * 64;
            #pragma unroll
            for (int i = 0; i < 8; i++) {
                int li = tid + i * 256;
                int m = li >> 4, c4 = li & 15;
                float4 va = *reinterpret_cast<const float4*>(Ab + (size_t)m * K + ko + c4 * 4);
                ar[i] = make_uint2(f2h2(va.x, va.y), f2h2(va.z, va.w));
                float4 vb = *reinterpret_cast<const float4*>(Wb + (size_t)m * K + ko + c4 * 4);
                br[i] = make_uint2(f2h2(vb.x, vb.y), f2h2(vb.z, vb.w));
            }
        }
        #pragma unroll
        for (int ks = 0; ks < 4; ks++) {
            int kb = ks * 16;
            unsigned a[4][4];
            #pragma unroll
            for (int am = 0; am < 4; am++) {
                int row = wm * 64 + am * 16;
                a[am][0] = *reinterpret_cast<const unsigned*>(&sm.As[buf][row + g][kb + 2 * t]);
                a[am][1] = *reinterpret_cast<const unsigned*>(&sm.As[buf][row + 8 + g][kb + 2 * t]);
                a[am][2] = *reinterpret_cast<const unsigned*>(&sm.As[buf][row + g][kb + 8 + 2 * t]);
                a[am][3] = *reinterpret_cast<const unsigned*>(&sm.As[buf][row + 8 + g][kb + 8 + 2 * t]);
            }
            unsigned b[4][2];
            #pragma unroll
            for (int an = 0; an < 4; an++) {
                int col = wn * 32 + an * 8 + g;
                b[an][0] = *reinterpret_cast<const unsigned*>(&sm.Bs[buf][col][kb + 2 * t]);
                b[an][1] = *reinterpret_cast<const unsigned*>(&sm.Bs[buf][col][kb + 8 + 2 * t]);
            }
            #pragma unroll
            for (int am = 0; am < 4; am++)
                #pragma unroll
                for (int an = 0; an < 4; an++)
                    mma16(acc[am][an], a[am][0], a[am][1], a[am][2], a[am][3],
                          b[an][0], b[an][1]);
        }
        if (kt + 1 < NKT) {
            int nb = buf ^ 1;
            #pragma unroll
            for (int i = 0; i < 8; i++) {
                int li = tid + i * 256;
                int m = li >> 4, c4 = li & 15;
                *reinterpret_cast<uint2*>(&sm.As[nb][m][c4 * 4]) = ar[i];
                *reinterpret_cast<uint2*>(&sm.Bs[nb][m][c4 * 4]) = br[i];
            }
        }
        __syncthreads();
    }
    #pragma unroll
    for (int am = 0; am < 4; am++) {
        int m = m0 + wm * 64 + am * 16 + g;
        #pragma unroll
        for (int an = 0; an < 4; an++) {
            int n = n0 + wn * 32 + an * 8 + 2 * t;
            float2 bv = *reinterpret_cast<const float2*>(bi + n);
            float v0 = (acc[am][an][0] + bv.x) * scale;
            float v1 = (acc[am][an][1] + bv.y) * scale;
            float v2 = (acc[am][an][2] + bv.x) * scale;
            float v3 = (acc[am][an][3] + bv.y) * scale;
            *reinterpret_cast<unsigned*>(C + (size_t)m * N + n) = f2h2(v0, v1);
            *reinterpret_cast<unsigned*>(C + (size_t)(m + 8) * N + n) = f2h2(v2, v3);
        }
    }
}

// ---------------------------------------------------------------------------
// Out projection: out = ctxh(fp16) @ wo^T + bo, fp32 output.
// ---------------------------------------------------------------------------
__global__ __launch_bounds__(256)
void gemm_out(const __half* __restrict__ Ah, const float* __restrict__ W,
              const float* __restrict__ bias, float* __restrict__ C,
              int M, int N, int K)
{
    extern __shared__ char smem_raw[];
    GemmSmem& sm = *reinterpret_cast<GemmSmem*>(smem_raw);
    int tid = threadIdx.x, lane = tid & 31, warp = tid >> 5;
    int g = lane >> 2, t = lane & 3;
    int wm = warp >> 2, wn = warp & 3;
    int m0 = blockIdx.y * 128, n0 = blockIdx.x * 128;
    const __half* Ab = Ah + (size_t)m0 * K;
    const float*  Wb = W + (size_t)n0 * K;
    float acc[4][4][4] = {};

    #pragma unroll
    for (int i = 0; i < 4; i++) {
        int li = tid + i * 256;
        int m = li >> 3, c8 = li & 7;
        *reinterpret_cast<uint4*>(&sm.As[0][m][c8 * 8]) =
            *reinterpret_cast<const uint4*>(Ab + (size_t)m * K + c8 * 8);
    }
    #pragma unroll
    for (int i = 0; i < 8; i++) {
        int li = tid + i * 256;
        int m = li >> 4, c4 = li & 15;
        float4 vb = *reinterpret_cast<const float4*>(Wb + (size_t)m * K + c4 * 4);
        *reinterpret_cast<uint2*>(&sm.Bs[0][m][c4 * 4]) =
            make_uint2(f2h2(vb.x, vb.y), f2h2(vb.z, vb.w));
    }
    __syncthreads();

    const int NKT = K / 64;
    for (int kt = 0; kt < NKT; kt++) {
        int buf = kt & 1;
        uint4 a4[4];
        uint2 br[8];
        if (kt + 1 < NKT) {
            int ko = (kt + 1) * 64;
            #pragma unroll
            for (int i = 0; i < 4; i++) {
                int li = tid + i * 256;
                int m = li >> 3, c8 = li & 7;
                a4[i] = *reinterpret_cast<const uint4*>(Ab + (size_t)m * K + ko + c8 * 8);
            }
            #pragma unroll
            for (int i = 0; i < 8; i++) {
                int li = tid + i * 256;
                int m = li >> 4, c4 = li & 15;
                float4 vb = *reinterpret_cast<const float4*>(Wb + (size_t)m * K + ko + c4 * 4);
                br[i] = make_uint2(f2h2(vb.x, vb.y), f2h2(vb.z, vb.w));
            }
        }
        #pragma unroll
        for (int ks = 0; ks < 4; ks++) {
            int kb = ks * 16;
            unsigned a[4][4];
            #pragma unroll
            for (int am = 0; am < 4; am++) {
                int row = wm * 64 + am * 16;
                a[am][0] = *reinterpret_cast<const unsigned*>(&sm.As[buf][row + g][kb + 2 * t]);
                a[am][1] = *reinterpret_cast<const unsigned*>(&sm.As[buf][row + 8 + g][kb + 2 * t]);
                a[am][2] = *reinterpret_cast<const unsigned*>(&sm.As[buf][row + g][kb + 8 + 2 * t]);
                a[am][3] = *reinterpret_cast<const unsigned*>(&sm.As[buf][row + 8 + g][kb + 8 + 2 * t]);
            }
            unsigned b[4][2];
            #pragma unroll
            for (int an = 0; an < 4; an++) {
                int col = wn * 32 + an * 8 + g;
                b[an][0] = *reinterpret_cast<const unsigned*>(&sm.Bs[buf][col][kb + 2 * t]);
                b[an][1] = *reinterpret_cast<const unsigned*>(&sm.Bs[buf][col][kb + 8 + 2 * t]);
            }
            #pragma unroll
            for (int am = 0; am < 4; am++)
                #pragma unroll
                for (int an = 0; an < 4; an++)
                    mma16(acc[am][an], a[am][0], a[am][1], a[am][2], a[am][3],
                          b[an][0], b[an][1]);
        }
        if (kt + 1 < NKT) {
            int nb = buf ^ 1;
            #pragma unroll
            for (int i = 0; i < 4; i++) {
                int li = tid + i * 256;
                int m = li >> 3, c8 = li & 7;
                *reinterpret_cast<uint4*>(&sm.As[nb][m][c8 * 8]) = a4[i];
            }
            #pragma unroll
            for (int i = 0; i < 8; i++) {
                int li = tid + i * 256;
                int m = li >> 4, c4 = li & 15;
                *reinterpret_cast<uint2*>(&sm.Bs[nb][m][c4 * 4]) = br[i];
            }
        }
        __syncthreads();
    }
    #pragma unroll
    for (int am = 0; am < 4; am++) {
        int m = m0 + wm * 64 + am * 16 + g;
        #pragma unroll
        for (int an = 0; an < 4; an++) {
            int n = n0 + wn * 32 + an * 8 + 2 * t;
            float2 bv = *reinterpret_cast<const float2*>(bias + n);
            *reinterpret_cast<float2*>(C + (size_t)m * N + n) =
                make_float2(acc[am][an][0] + bv.x, acc[am][an][1] + bv.y);
            *reinterpret_cast<float2*>(C + (size_t)(m + 8) * N + n) =
                make_float2(acc[am][an][2] + bv.x, acc[am][an][3] + bv.y);
        }
    }
}

// ---------------------------------------------------------------------------
// V transpose: vh [t][b][e] fp16 -> vt [(b*EMB+e)][t] fp16. 32x32 smem tiles.
// ---------------------------------------------------------------------------
__global__ __launch_bounds__(256)
void v_transpose(const __half* __restrict__ vh, __half* __restrict__ vt)
{
    __shared__ __half ts[32][33];
    int t0 = blockIdx.x * 32, e0 = blockIdx.y * 32, b = blockIdx.z;
    int tx = threadIdx.x & 31, ty = threadIdx.x >> 5;   // 32 x 8
    #pragma unroll
    for (int j = 0; j < 4; j++) {
        int r = ty * 4 + j;
        ts[r][tx] = vh[((size_t)(t0 + r) * BSZ + b) * EMB + e0 + tx];
    }
    __syncthreads();
    #pragma unroll
    for (int j = 0; j < 4; j++) {
        int r = ty * 4 + j;
        vt[((size_t)b * EMB + e0 + r) * TGT + t0 + tx] = ts[tx][r];
    }
}

// ---------------------------------------------------------------------------
// Fused flash attention (fp16 mma), cp.async pipelined. Unchanged from R11.
// ---------------------------------------------------------------------------
struct FusedSmem {
    unsigned short Qs[128][SKH];     // Q tile; reused as E staging after hoist
    unsigned short Ks[2][64][SKH];
    unsigned short Vs[2][64][SKH];   // [dim][token]
    float lsum[128];
};
#define FUSED_SMEM ((int)sizeof(FusedSmem))

__global__ __launch_bounds__(128, 3)
void attn_fused(const __half* __restrict__ qh, const __half* __restrict__ kh,
                const __half* __restrict__ vt, __half* __restrict__ ctxh,
                float* __restrict__ linv, __half* __restrict__ eg)
{
    extern __shared__ char smem_raw[];
    FusedSmem& sm = *reinterpret_cast<FusedSmem*>(smem_raw);
    const int LDA = BSZ * EMB;
    int tid = threadIdx.x, lane = tid & 31;
    int wm = tid >> 5;
    int g = lane >> 2, t = lane & 3;
    int z = blockIdx.y;
    int b = z / NH, h = z % NH;
    int m0 = blockIdx.x * 128;
    const __half* Qb = qh + (size_t)b * EMB + h * HD;
    const __half* Kb = kh + (size_t)b * EMB + h * HD;
    const __half* Vb = vt + ((size_t)b * EMB + h * HD) * TGT;
    __half* Ez = eg + (size_t)z * TT;

    #pragma unroll
    for (int i = 0; i < 8; i++) {
        int li = tid + i * 128;
        int r = li >> 3, c8 = li & 7;
        cp16(&sm.Qs[r][c8 * 8], Qb + (size_t)(m0 + r) * LDA + c8 * 8);
    }
    #pragma unroll
    for (int i = 0; i < 4; i++) {
        int li = tid + i * 128;
        int r = li >> 3, c8 = li & 7;
        cp16(&sm.Ks[0][r][c8 * 8], Kb + (size_t)r * LDA + c8 * 8);
        cp16(&sm.Vs[0][r][c8 * 8], Vb + (size_t)r * TGT + c8 * 8);
    }
    CP_COMMIT();
    CP_WAIT0();
    __syncthreads();

    unsigned qf[2][4][4];
    #pragma unroll
    for (int am = 0; am < 2; am++) {
        int row = wm * 32 + am * 16;
        #pragma unroll
        for (int ks = 0; ks < 4; ks++) {
            int kb = ks * 16;
            qf[am][ks][0] = *reinterpret_cast<const unsigned*>(&sm.Qs[row + g][kb + 2 * t]);
            qf[am][ks][1] = *reinterpret_cast<const unsigned*>(&sm.Qs[row + 8 + g][kb + 2 * t]);
            qf[am][ks][2] = *reinterpret_cast<const unsigned*>(&sm.Qs[row + g][kb + 8 + 2 * t]);
            qf[am][ks][3] = *reinterpret_cast<const unsigned*>(&sm.Qs[row + 8 + g][kb + 8 + 2 * t]);
        }
    }

    float acc_c[2][8][4] = {};
    float lp[4] = {};

    for (int nt = 0; nt < TGT / 64; nt++) {
        int buf = nt & 1;
        bool hasNext = (nt + 1) < TGT / 64;
        if (hasNext) {
            int n1 = (nt + 1) * 64;
            int nb = buf ^ 1;
            #pragma unroll
            for (int i = 0; i < 4; i++) {
                int li = tid + i * 128;
                int r = li >> 3, c8 = li & 7;
                cp16(&sm.Ks[nb][r][c8 * 8], Kb + (size_t)(n1 + r) * LDA + c8 * 8);
                cp16(&sm.Vs[nb][r][c8 * 8], Vb + (size_t)r * TGT + n1 + c8 * 8);
            }
            CP_COMMIT();
        }

        float acc_s[2][8][4] = {};
        #pragma unroll
        for (int ks = 0; ks < 4; ks++) {
            int kb = ks * 16;
            unsigned bb[8][2];
            #pragma unroll
            for (int an = 0; an < 8; an++) {
                int col = an * 8 + g;
                bb[an][0] = *reinterpret_cast<const unsigned*>(&sm.Ks[buf][col][kb + 2 * t]);
                bb[an][1] = *reinterpret_cast<const unsigned*>(&sm.Ks[buf][col][kb + 8 + 2 * t]);
            }
            #pragma unroll
            for (int am = 0; am < 2; am++)
                #pragma unroll
                for (int an = 0; an < 8; an++)
                    mma16(acc_s[am][an], qf[am][ks][0], qf[am][ks][1],
                          qf[am][ks][2], qf[am][ks][3], bb[an][0], bb[an][1]);
        }

        unsigned eh[2][16];
        #pragma unroll
        for (int am = 0; am < 2; am++) {
            #pragma unroll
            for (int an = 0; an < 8; an++) {
                float e0 = __expf(acc_s[am][an][0]);
                float e1 = __expf(acc_s[am][an][1]);
                float e2 = __expf(acc_s[am][an][2]);
                float e3 = __expf(acc_s[am][an][3]);
                lp[am * 2 + 0] += e0 + e1;
                lp[am * 2 + 1] += e2 + e3;
                eh[am][2 * an + 0] = f2h2(e0, e1);
                eh[am][2 * an + 1] = f2h2(e2, e3);
            }
        }

        #pragma unroll
        for (int ks = 0; ks < 4; ks++) {
            int kb = ks * 16;
            unsigned bb[8][2];
            #pragma unroll
            for (int an = 0; an < 8; an++) {
                int col = an * 8 + g;
                bb[an][0] = *reinterpret_cast<const unsigned*>(&sm.Vs[buf][col][kb + 2 * t]);
                bb[an][1] = *reinterpret_cast<const unsigned*>(&sm.Vs[buf][col][kb + 8 + 2 * t]);
            }
            #pragma unroll
            for (int am = 0; am < 2; am++)
                #pragma unroll
                for (int an = 0; an < 8; an++)
                    mma16(acc_c[am][an], eh[am][4 * ks + 0], eh[am][4 * ks + 1],
                          eh[am][4 * ks + 2], eh[am][4 * ks + 3],
                          bb[an][0], bb[an][1]);
        }

        #pragma unroll
        for (int am = 0; am < 2; am++) {
            int r0 = wm * 32 + am * 16 + g;
            #pragma unroll
            for (int an = 0; an < 8; an++) {
                int c = an * 8 + 2 * t;
                *reinterpret_cast<unsigned*>(&sm.Qs[r0][c]) = eh[am][2 * an];
                *reinterpret_cast<unsigned*>(&sm.Qs[r0 + 8][c]) = eh[am][2 * an + 1];
            }
        }
        __syncwarp();
        {
            int n0 = nt * 64;
            int rb = wm * 32 + (lane >> 4);
            int c4 = lane & 15;
            #pragma unroll
            for (int i = 0; i < 16; i++) {
                int row = rb + i * 2;
                uint2 d = *reinterpret_cast<const uint2*>(&sm.Qs[row][c4 * 4]);
                *reinterpret_cast<uint2*>(Ez + (size_t)(m0 + row) * TGT + n0 + c4 * 4) = d;
            }
        }

        if (hasNext) CP_WAIT0();
        __syncthreads();
    }

    #pragma unroll
    for (int r4 = 0; r4 < 4; r4++) {
        float s = lp[r4];
        s += __shfl_xor_sync(0xffffffff, s, 1);
        s += __shfl_xor_sync(0xffffffff, s, 2);
        if (t == 0)
            sm.lsum[wm * 32 + (r4 >> 1) * 16 + (r4 & 1) * 8 + g] = s;
    }
    __syncthreads();
    {
        float inv = 1.0f / sm.lsum[tid];
        linv[(size_t)z * TGT + m0 + tid] = inv;
        sm.lsum[tid] = inv;
    }
    __syncthreads();

    #pragma unroll
    for (int am = 0; am < 2; am++) {
        int rloc = wm * 32 + am * 16 + g;
        float inv0 = sm.lsum[rloc];
        float inv1 = sm.lsum[rloc + 8];
        int m = m0 + rloc;
        #pragma unroll
        for (int an = 0; an < 8; an++) {
            int n = an * 8 + 2 * t;
            __half* c0 = ctxh + ((size_t)m * BSZ + b) * EMB + h * HD + n;
            __half* c1 = ctxh + ((size_t)(m + 8) * BSZ + b) * EMB + h * HD + n;
            *reinterpret_cast<unsigned*>(c0) =
                f2h2(acc_c[am][an][0] * inv0, acc_c[am][an][1] * inv0);
            *reinterpret_cast<unsigned*>(c1) =
                f2h2(acc_c[am][an][2] * inv1, acc_c[am][an][3] * inv1);
        }
    }
}

// ---------------------------------------------------------------------------
// avg_reduce: avg[b,m,n] = (1/NH) sum_h E_h[m,n] * linv_h[m]. Memory-bound.
// ---------------------------------------------------------------------------
__global__ __launch_bounds__(256)
void avg_reduce(const __half* __restrict__ eg, const float* __restrict__ linv,
                float* __restrict__ avg)
{
    int mrow = blockIdx.x;
    int b = blockIdx.y;
    int tid = threadIdx.x;
    __shared__ float sl[NH];
    if (tid < NH) sl[tid] = linv[(size_t)(b * NH + tid) * TGT + mrow];
    __syncthreads();

    float a0x = 0.f, a0y = 0.f, a1x = 0.f, a1y = 0.f;
    float a2x = 0.f, a2y = 0.f, a3x = 0.f, a3y = 0.f;
    #pragma unroll
    for (int h = 0; h < NH; h++) {
        const float4* rowp = reinterpret_cast<const float4*>(
            eg + (size_t)(b * NH + h) * TT + (size_t)mrow * TGT);
        float4 raw = rowp[tid];
        const __half2* hp = reinterpret_cast<const __half2*>(&raw);
        float lv = sl[h];
        float2 f0 = __half22float2(hp[0]);
        float2 f1 = __half22float2(hp[1]);
        float2 f2 = __half22float2(hp[2]);
        float2 f3 = __half22float2(hp[3]);
        a0x += f0.x * lv; a0y += f0.y * lv;
        a1x += f1.x * lv; a1y += f1.y * lv;
        a2x += f2.x * lv; a2y += f2.y * lv;
        a3x += f3.x * lv; a3y += f3.y * lv;
    }
    const float invH = 1.0f / NH;
    float* op = avg + (size_t)b * TT + (size_t)mrow * TGT + tid * 8;
    *reinterpret_cast<float4*>(op) =
        make_float4(a0x * invH, a0y * invH, a1x * invH, a1y * invH);
    *reinterpret_cast<float4*>(op + 4) =
        make_float4(a2x * invH, a2y * invH, a3x * invH, a3y * invH);
}

extern "C" void kernel_launch(void* const* d_in, const int* in_sizes, int n_in,
                              void* d_out, int out_size)
{
    const float* x  = (const float*)d_in[0];
    const float* wq = (const float*)d_in[1];
    const float* bq = (const float*)d_in[2];
    const float* wk = (const float*)d_in[3];
    const float* bk = (const float*)d_in[4];
    const float* wv = (const float*)d_in[5];
    const float* bv = (const float*)d_in[6];
    const float* wo = (const float*)d_in[7];
    const float* bo = (const float*)d_in[8];
    float* out = (float*)d_out;
    float* avg = out + (size_t)MROWS * EMB;

    __half *qh, *kh, *vh, *vt, *ctxh, *eg;
    float *linv;
    cudaGetSymbolAddress((void**)&qh,   g_qh);
    cudaGetSymbolAddress((void**)&kh,   g_kh);
    cudaGetSymbolAddress((void**)&vh,   g_vh);
    cudaGetSymbolAddress((void**)&vt,   g_vt);
    cudaGetSymbolAddress((void**)&ctxh, g_ctxh);
    cudaGetSymbolAddress((void**)&linv, g_linv);
    cudaGetSymbolAddress((void**)&eg,   g_e);

    cudaFuncSetAttribute(attn_fused, cudaFuncAttributeMaxDynamicSharedMemorySize, FUSED_SMEM);
    cudaFuncSetAttribute(gemm_qkv, cudaFuncAttributeMaxDynamicSharedMemorySize, GEMM_SMEM);
    cudaFuncSetAttribute(gemm_out, cudaFuncAttributeMaxDynamicSharedMemorySize, GEMM_SMEM);

    cudaStream_t s1;
    cudaStreamCreateWithFlags(&s1, cudaStreamNonBlocking);
    cudaEvent_t ev1, ev2;
    cudaEventCreateWithFlags(&ev1, cudaEventDisableTiming);
    cudaEventCreateWithFlags(&ev2, cudaEventDisableTiming);

    // merged QKV projection: one launch, grid (8, 64, 3)
    dim3 gqkv(EMB / 128, MROWS / 128, 3);
    gemm_qkv<<<gqkv, 256, GEMM_SMEM>>>(x, wq, bq, wk, bk, wv, bv, qh, kh, vh);

    dim3 gtr(TGT / 32, EMB / 32, BSZ);       // (64, 32, 4)
    v_transpose<<<gtr, 256>>>(vh, vt);

    dim3 gfused(TGT / 128, BH);              // (16, 64)
    attn_fused<<<gfused, 128, FUSED_SMEM>>>(qh, kh, vt, ctxh, linv, eg);

    // fork: avg_reduce || out-projection
    cudaEventRecord(ev1, 0);
    cudaStreamWaitEvent(s1, ev1, 0);
    dim3 gavg(TGT, BSZ);                     // (2048, 4)
    avg_reduce<<<gavg, 256, 0, s1>>>(eg, linv, avg);
    cudaEventRecord(ev2, s1);

    dim3 gproj(EMB / 128, MROWS / 128);      // (8, 64)
    gemm_out<<<gproj, 256, GEMM_SMEM>>>(ctxh, wo, bo, out, MROWS, EMB, EMB);

    cudaStreamWaitEvent(0, ev2, 0);

    cudaEventDestroy(ev1);
    cudaEventDestroy(ev2);
    cudaStreamDestroy(s1);
}

// round 13
// speedup vs baseline: 1.0705x; 1.0705x over previous
#include <cuda_runtime.h>
#include <cuda_fp16.h>
#include <cstdint>
#include <math.h>

#define TGT 2048
#define BSZ 4
#define EMB 1024
#define NH  16
#define HD  64
#define MROWS (TGT * BSZ)          // 8192
#define BH (BSZ * NH)              // 64
#define SKH 72                     // padded half-stride for 64-wide fp16 tiles
#define TT ((size_t)TGT * TGT)

// scratch (device globals: allocation-free per harness rules). uint4 for alignment.
__device__ uint4 g_qh[(size_t)MROWS * EMB / 8];      // fp16 q   [t][b][e]
__device__ uint4 g_kh[(size_t)MROWS * EMB / 8];      // fp16 k   [t][b][e]
__device__ uint4 g_vh[(size_t)MROWS * EMB / 8];      // fp16 v   [t][b][e]
__device__ uint4 g_vt[(size_t)MROWS * EMB / 8];      // fp16 v^T [b*EMB+e][t]
__device__ uint4 g_ctxh[(size_t)MROWS * EMB / 8];    // fp16 ctx [t][b][e]
__device__ float g_linv[(size_t)BH * TGT];           // 1/rowsum(exp S)
__device__ uint4 g_e[BH * TT / 8];                   // E=exp(S) fp16, 536 MB

// ---------------------------------------------------------------------------
// helpers
// ---------------------------------------------------------------------------
__device__ __forceinline__ unsigned f2h2(float a, float b) {
    __half2 h = __floats2half2_rn(a, b);
    return *reinterpret_cast<unsigned*>(&h);
}

__device__ __forceinline__ void mma16(float* c,
                                      unsigned a0, unsigned a1, unsigned a2, unsigned a3,
                                      unsigned b0, unsigned b1) {
    asm volatile(
        "mma.sync.aligned.m16n8k16.row.col.f32.f16.f16.f32 "
        "{%0,%1,%2,%3}, {%4,%5,%6,%7}, {%8,%9}, {%0,%1,%2,%3};\n"
        : "+f"(c[0]), "+f"(c[1]), "+f"(c[2]), "+f"(c[3])
        : "r"(a0), "r"(a1), "r"(a2), "r"(a3), "r"(b0), "r"(b1));
}

__device__ __forceinline__ void cp16(void* dst, const void* src) {
    uint32_t d = (uint32_t)__cvta_generic_to_shared(dst);
    asm volatile("cp.async.cg.shared.global [%0], [%1], 16;\n" :: "r"(d), "l"(src));
}
#define CP_COMMIT() asm volatile("cp.async.commit_group;\n" ::: "memory")
#define CP_WAIT0()  asm volatile("cp.async.wait_group 0;\n" ::: "memory")

// ---------------------------------------------------------------------------
// Projection GEMM (fp16 mma, double-buffered): C = (A @ W^T + bias) * scale
// AH: A is fp16 (else fp32). CH: C written fp16 (else fp32).
// BM=BN=128, BK=64. 256 threads = 8 warps (2 m x 4 n), warp tile 64x32.
// ---------------------------------------------------------------------------
struct GemmSmem {
    unsigned short As[2][128][SKH];
    unsigned short Bs[2][128][SKH];
};
#define GEMM_SMEM ((int)sizeof(GemmSmem))

template<int AH, int CH>
__global__ __launch_bounds__(256)
void gemm_nt(const void* __restrict__ Av, const float* __restrict__ W,
             const float* __restrict__ bias, void* __restrict__ Cv,
             int M, int N, int K, float scale)
{
    extern __shared__ char smem_raw[];
    GemmSmem& sm = *reinterpret_cast<GemmSmem*>(smem_raw);
    int tid = threadIdx.x, lane = tid & 31, warp = tid >> 5;
    int g = lane >> 2, t = lane & 3;
    int wm = warp >> 2, wn = warp & 3;
    int m0 = blockIdx.y * 128, n0 = blockIdx.x * 128;
    const float*  Af = (const float*)Av + (size_t)m0 * K;
    const __half* Ah = (const __half*)Av + (size_t)m0 * K;
    const float*  Wb = W + (size_t)n0 * K;
    float acc[4][4][4] = {};

    // stage k-tile 0
    if (AH) {
        #pragma unroll
        for (int i = 0; i < 4; i++) {
            int li = tid + i * 256;
            int m = li >> 3, c8 = li & 7;
            *reinterpret_cast<uint4*>(&sm.As[0][m][c8 * 8]) =
                *reinterpret_cast<const uint4*>(Ah + (size_t)m * K + c8 * 8);
        }
    } else {
        #pragma unroll
        for (int i = 0; i < 8; i++) {
            int li = tid + i * 256;
            int m = li >> 4, c4 = li & 15;
            float4 va = *reinterpret_cast<const float4*>(Af + (size_t)m * K + c4 * 4);
            *reinterpret_cast<uint2*>(&sm.As[0][m][c4 * 4]) =
                make_uint2(f2h2(va.x, va.y), f2h2(va.z, va.w));
        }
    }
    #pragma unroll
    for (int i = 0; i < 8; i++) {
        int li = tid + i * 256;
        int m = li >> 4, c4 = li & 15;
        float4 vb = *reinterpret_cast<const float4*>(Wb + (size_t)m * K + c4 * 4);
        *reinterpret_cast<uint2*>(&sm.Bs[0][m][c4 * 4]) =
            make_uint2(f2h2(vb.x, vb.y), f2h2(vb.z, vb.w));
    }
    __syncthreads();

    const int NKT = K / 64;   // 16
    for (int kt = 0; kt < NKT; kt++) {
        int buf = kt & 1;
        uint4 a4[4];
        uint2 ar[8], br[8];
        if (kt + 1 < NKT) {
            int ko = (kt + 1) * 64;
            if (AH) {
                #pragma unroll
                for (int i = 0; i < 4; i++) {
                    int li = tid + i * 256;
                    int m = li >> 3, c8 = li & 7;
                    a4[i] = *reinterpret_cast<const uint4*>(Ah + (size_t)m * K + ko + c8 * 8);
                }
            } else {
                #pragma unroll
                for (int i = 0; i < 8; i++) {
                    int li = tid + i * 256;
                    int m = li >> 4, c4 = li & 15;
                    float4 va = *reinterpret_cast<const float4*>(Af + (size_t)m * K + ko + c4 * 4);
                    ar[i] = make_uint2(f2h2(va.x, va.y), f2h2(va.z, va.w));
                }
            }
            #pragma unroll
            for (int i = 0; i < 8; i++) {
                int li = tid + i * 256;
                int m = li >> 4, c4 = li & 15;
                float4 vb = *reinterpret_cast<const float4*>(Wb + (size_t)m * K + ko + c4 * 4);
                br[i] = make_uint2(f2h2(vb.x, vb.y), f2h2(vb.z, vb.w));
            }
        }
        #pragma unroll
        for (int ks = 0; ks < 4; ks++) {
            int kb = ks * 16;
            unsigned a[4][4];
            #pragma unroll
            for (int am = 0; am < 4; am++) {
                int row = wm * 64 + am * 16;
                a[am][0] = *reinterpret_cast<const unsigned*>(&sm.As[buf][row + g][kb + 2 * t]);
                a[am][1] = *reinterpret_cast<const unsigned*>(&sm.As[buf][row + 8 + g][kb + 2 * t]);
                a[am][2] = *reinterpret_cast<const unsigned*>(&sm.As[buf][row + g][kb + 8 + 2 * t]);
                a[am][3] = *reinterpret_cast<const unsigned*>(&sm.As[buf][row + 8 + g][kb + 8 + 2 * t]);
            }
            unsigned b[4][2];
            #pragma unroll
            for (int an = 0; an < 4; an++) {
                int col = wn * 32 + an * 8 + g;
                b[an][0] = *reinterpret_cast<const unsigned*>(&sm.Bs[buf][col][kb + 2 * t]);
                b[an][1] = *reinterpret_cast<const unsigned*>(&sm.Bs[buf][col][kb + 8 + 2 * t]);
            }
            #pragma unroll
            for (int am = 0; am < 4; am++)
                #pragma unroll
                for (int an = 0; an < 4; an++)
                    mma16(acc[am][an], a[am][0], a[am][1], a[am][2], a[am][3],
                          b[an][0], b[an][1]);
        }
        if (kt + 1 < NKT) {
            int nb = buf ^ 1;
            if (AH) {
                #pragma unroll
                for (int i = 0; i < 4; i++) {
                    int li = tid + i * 256;
                    int m = li >> 3, c8 = li & 7;
                    *reinterpret_cast<uint4*>(&sm.As[nb][m][c8 * 8]) = a4[i];
                }
            } else {
                #pragma unroll
                for (int i = 0; i < 8; i++) {
                    int li = tid + i * 256;
                    int m = li >> 4, c4 = li & 15;
                    *reinterpret_cast<uint2*>(&sm.As[nb][m][c4 * 4]) = ar[i];
                }
            }
            #pragma unroll
            for (int i = 0; i < 8; i++) {
                int li = tid + i * 256;
                int m = li >> 4, c4 = li & 15;
                *reinterpret_cast<uint2*>(&sm.Bs[nb][m][c4 * 4]) = br[i];
            }
        }
        __syncthreads();
    }
    #pragma unroll
    for (int am = 0; am < 4; am++) {
        int m = m0 + wm * 64 + am * 16 + g;
        #pragma unroll
        for (int an = 0; an < 4; an++) {
            int n = n0 + wn * 32 + an * 8 + 2 * t;
            float2 bv = *reinterpret_cast<const float2*>(bias + n);
            float v0 = (acc[am][an][0] + bv.x) * scale;
            float v1 = (acc[am][an][1] + bv.y) * scale;
            float v2 = (acc[am][an][2] + bv.x) * scale;
            float v3 = (acc[am][an][3] + bv.y) * scale;
            if (CH) {
                __half* Ch = (__half*)Cv;
                *reinterpret_cast<unsigned*>(Ch + (size_t)m * N + n) = f2h2(v0, v1);
                *reinterpret_cast<unsigned*>(Ch + (size_t)(m + 8) * N + n) = f2h2(v2, v3);
            } else {
                float* Cf = (float*)Cv;
                *reinterpret_cast<float2*>(Cf + (size_t)m * N + n) = make_float2(v0, v1);
                *reinterpret_cast<float2*>(Cf + (size_t)(m + 8) * N + n) = make_float2(v2, v3);
            }
        }
    }
}

// ---------------------------------------------------------------------------
// V transpose: vh [t][b][e] fp16 -> vt [(b*EMB+e)][t] fp16. 32x32 smem tiles.
// ---------------------------------------------------------------------------
__global__ __launch_bounds__(256)
void v_transpose(const __half* __restrict__ vh, __half* __restrict__ vt)
{
    __shared__ __half ts[32][33];
    int t0 = blockIdx.x * 32, e0 = blockIdx.y * 32, b = blockIdx.z;
    int tx = threadIdx.x & 31, ty = threadIdx.x >> 5;   // 32 x 8
    #pragma unroll
    for (int j = 0; j < 4; j++) {
        int r = ty * 4 + j;
        ts[r][tx] = vh[((size_t)(t0 + r) * BSZ + b) * EMB + e0 + tx];
    }
    __syncthreads();
    #pragma unroll
    for (int j = 0; j < 4; j++) {
        int r = ty * 4 + j;   // e within tile
        vt[((size_t)b * EMB + e0 + r) * TGT + t0 + tx] = ts[tx][r];
    }
}

// ---------------------------------------------------------------------------
// Fused flash attention (fp16 mma), cp.async pipelined (R11 structure).
// Change vs R11: E gmem store issued BEFORE the PV mma so STG drains
// concurrently with tensor work.
// ---------------------------------------------------------------------------
struct FusedSmem {
    unsigned short Qs[128][SKH];     // Q tile; reused as E staging after hoist
    unsigned short Ks[2][64][SKH];
    unsigned short Vs[2][64][SKH];   // [dim][token]
    float lsum[128];
};
#define FUSED_SMEM ((int)sizeof(FusedSmem))

__global__ __launch_bounds__(128, 3)
void attn_fused(const __half* __restrict__ qh, const __half* __restrict__ kh,
                const __half* __restrict__ vt, __half* __restrict__ ctxh,
                float* __restrict__ linv, __half* __restrict__ eg)
{
    extern __shared__ char smem_raw[];
    FusedSmem& sm = *reinterpret_cast<FusedSmem*>(smem_raw);
    const int LDA = BSZ * EMB;
    int tid = threadIdx.x, lane = tid & 31;
    int wm = tid >> 5;
    int g = lane >> 2, t = lane & 3;
    int z = blockIdx.y;
    int b = z / NH, h = z % NH;
    int m0 = blockIdx.x * 128;
    const __half* Qb = qh + (size_t)b * EMB + h * HD;
    const __half* Kb = kh + (size_t)b * EMB + h * HD;
    const __half* Vb = vt + ((size_t)b * EMB + h * HD) * TGT;
    __half* Ez = eg + (size_t)z * TT;

    #pragma unroll
    for (int i = 0; i < 8; i++) {
        int li = tid + i * 128;
        int r = li >> 3, c8 = li & 7;
        cp16(&sm.Qs[r][c8 * 8], Qb + (size_t)(m0 + r) * LDA + c8 * 8);
    }
    #pragma unroll
    for (int i = 0; i < 4; i++) {
        int li = tid + i * 128;
        int r = li >> 3, c8 = li & 7;
        cp16(&sm.Ks[0][r][c8 * 8], Kb + (size_t)r * LDA + c8 * 8);
        cp16(&sm.Vs[0][r][c8 * 8], Vb + (size_t)r * TGT + c8 * 8);
    }
    CP_COMMIT();
    CP_WAIT0();
    __syncthreads();

    unsigned qf[2][4][4];
    #pragma unroll
    for (int am = 0; am < 2; am++) {
        int row = wm * 32 + am * 16;
        #pragma unroll
        for (int ks = 0; ks < 4; ks++) {
            int kb = ks * 16;
            qf[am][ks][0] = *reinterpret_cast<const unsigned*>(&sm.Qs[row + g][kb + 2 * t]);
            qf[am][ks][1] = *reinterpret_cast<const unsigned*>(&sm.Qs[row + 8 + g][kb + 2 * t]);
            qf[am][ks][2] = *reinterpret_cast<const unsigned*>(&sm.Qs[row + g][kb + 8 + 2 * t]);
            qf[am][ks][3] = *reinterpret_cast<const unsigned*>(&sm.Qs[row + 8 + g][kb + 8 + 2 * t]);
        }
    }

    float acc_c[2][8][4] = {};
    float lp[4] = {};

    for (int nt = 0; nt < TGT / 64; nt++) {
        int buf = nt & 1;
        bool hasNext = (nt + 1) < TGT / 64;
        if (hasNext) {
            int n1 = (nt + 1) * 64;
            int nb = buf ^ 1;
            #pragma unroll
            for (int i = 0; i < 4; i++) {
                int li = tid + i * 128;
                int r = li >> 3, c8 = li & 7;
                cp16(&sm.Ks[nb][r][c8 * 8], Kb + (size_t)(n1 + r) * LDA + c8 * 8);
                cp16(&sm.Vs[nb][r][c8 * 8], Vb + (size_t)r * TGT + n1 + c8 * 8);
            }
            CP_COMMIT();
        }

        // S = Q K^T
        float acc_s[2][8][4] = {};
        #pragma unroll
        for (int ks = 0; ks < 4; ks++) {
            int kb = ks * 16;
            unsigned bb[8][2];
            #pragma unroll
            for (int an = 0; an < 8; an++) {
                int col = an * 8 + g;
                bb[an][0] = *reinterpret_cast<const unsigned*>(&sm.Ks[buf][col][kb + 2 * t]);
                bb[an][1] = *reinterpret_cast<const unsigned*>(&sm.Ks[buf][col][kb + 8 + 2 * t]);
            }
            #pragma unroll
            for (int am = 0; am < 2; am++)
                #pragma unroll
                for (int an = 0; an < 8; an++)
                    mma16(acc_s[am][an], qf[am][ks][0], qf[am][ks][1],
                          qf[am][ks][2], qf[am][ks][3], bb[an][0], bb[an][1]);
        }

        // E = exp(S) in registers (packed as PV A-fragments)
        unsigned eh[2][16];
        #pragma unroll
        for (int am = 0; am < 2; am++) {
            #pragma unroll
            for (int an = 0; an < 8; an++) {
                float e0 = __expf(acc_s[am][an][0]);
                float e1 = __expf(acc_s[am][an][1]);
                float e2 = __expf(acc_s[am][an][2]);
                float e3 = __expf(acc_s[am][an][3]);
                lp[am * 2 + 0] += e0 + e1;
                lp[am * 2 + 1] += e2 + e3;
                eh[am][2 * an + 0] = f2h2(e0, e1);
                eh[am][2 * an + 1] = f2h2(e2, e3);
            }
        }

        // E store FIRST (STG drains while PV mma runs below)
        #pragma unroll
        for (int am = 0; am < 2; am++) {
            int r0 = wm * 32 + am * 16 + g;
            #pragma unroll
            for (int an = 0; an < 8; an++) {
                int c = an * 8 + 2 * t;
                *reinterpret_cast<unsigned*>(&sm.Qs[r0][c]) = eh[am][2 * an];
                *reinterpret_cast<unsigned*>(&sm.Qs[r0 + 8][c]) = eh[am][2 * an + 1];
            }
        }
        __syncwarp();
        {
            int n0 = nt * 64;
            int rb = wm * 32 + (lane >> 4);
            int c4 = lane & 15;
            #pragma unroll
            for (int i = 0; i < 16; i++) {
                int row = rb + i * 2;
                uint2 d = *reinterpret_cast<const uint2*>(&sm.Qs[row][c4 * 4]);
                *reinterpret_cast<uint2*>(Ez + (size_t)(m0 + row) * TGT + n0 + c4 * 4) = d;
            }
        }

        // ctx += E @ V
        #pragma unroll
        for (int ks = 0; ks < 4; ks++) {
            int kb = ks * 16;
            unsigned bb[8][2];
            #pragma unroll
            for (int an = 0; an < 8; an++) {
                int col = an * 8 + g;
                bb[an][0] = *reinterpret_cast<const unsigned*>(&sm.Vs[buf][col][kb + 2 * t]);
                bb[an][1] = *reinterpret_cast<const unsigned*>(&sm.Vs[buf][col][kb + 8 + 2 * t]);
            }
            #pragma unroll
            for (int am = 0; am < 2; am++)
                #pragma unroll
                for (int an = 0; an < 8; an++)
                    mma16(acc_c[am][an], eh[am][4 * ks + 0], eh[am][4 * ks + 1],
                          eh[am][4 * ks + 2], eh[am][4 * ks + 3],
                          bb[an][0], bb[an][1]);
        }

        if (hasNext) CP_WAIT0();
        __syncthreads();
    }

    // row sums
    #pragma unroll
    for (int r4 = 0; r4 < 4; r4++) {
        float s = lp[r4];
        s += __shfl_xor_sync(0xffffffff, s, 1);
        s += __shfl_xor_sync(0xffffffff, s, 2);
        if (t == 0)
            sm.lsum[wm * 32 + (r4 >> 1) * 16 + (r4 & 1) * 8 + g] = s;
    }
    __syncthreads();
    {
        float inv = 1.0f / sm.lsum[tid];
        linv[(size_t)z * TGT + m0 + tid] = inv;
        sm.lsum[tid] = inv;
    }
    __syncthreads();

    // normalize + write ctx (fp16)
    #pragma unroll
    for (int am = 0; am < 2; am++) {
        int rloc = wm * 32 + am * 16 + g;
        float inv0 = sm.lsum[rloc];
        float inv1 = sm.lsum[rloc + 8];
        int m = m0 + rloc;
        #pragma unroll
        for (int an = 0; an < 8; an++) {
            int n = an * 8 + 2 * t;
            __half* c0 = ctxh + ((size_t)m * BSZ + b) * EMB + h * HD + n;
            __half* c1 = ctxh + ((size_t)(m + 8) * BSZ + b) * EMB + h * HD + n;
            *reinterpret_cast<unsigned*>(c0) =
                f2h2(acc_c[am][an][0] * inv0, acc_c[am][an][1] * inv0);
            *reinterpret_cast<unsigned*>(c1) =
                f2h2(acc_c[am][an][2] * inv1, acc_c[am][an][3] * inv1);
        }
    }
}

// ---------------------------------------------------------------------------
// avg_reduce: avg[b,m,n] = (1/NH) sum_h E_h[m,n] * linv_h[m]. Memory-bound.
// ---------------------------------------------------------------------------
__global__ __launch_bounds__(256)
void avg_reduce(const __half* __restrict__ eg, const float* __restrict__ linv,
                float* __restrict__ avg)
{
    int mrow = blockIdx.x;
    int b = blockIdx.y;
    int tid = threadIdx.x;
    __shared__ float sl[NH];
    if (tid < NH) sl[tid] = linv[(size_t)(b * NH + tid) * TGT + mrow];
    __syncthreads();

    float a0x = 0.f, a0y = 0.f, a1x = 0.f, a1y = 0.f;
    float a2x = 0.f, a2y = 0.f, a3x = 0.f, a3y = 0.f;
    #pragma unroll
    for (int h = 0; h < NH; h++) {
        const float4* rowp = reinterpret_cast<const float4*>(
            eg + (size_t)(b * NH + h) * TT + (size_t)mrow * TGT);
        float4 raw = rowp[tid];
        const __half2* hp = reinterpret_cast<const __half2*>(&raw);
        float lv = sl[h];
        float2 f0 = __half22float2(hp[0]);
        float2 f1 = __half22float2(hp[1]);
        float2 f2 = __half22float2(hp[2]);
        float2 f3 = __half22float2(hp[3]);
        a0x += f0.x * lv; a0y += f0.y * lv;
        a1x += f1.x * lv; a1y += f1.y * lv;
        a2x += f2.x * lv; a2y += f2.y * lv;
        a3x += f3.x * lv; a3y += f3.y * lv;
    }
    const float invH = 1.0f / NH;
    float* op = avg + (size_t)b * TT + (size_t)mrow * TGT + tid * 8;
    *reinterpret_cast<float4*>(op) =
        make_float4(a0x * invH, a0y * invH, a1x * invH, a1y * invH);
    *reinterpret_cast<float4*>(op + 4) =
        make_float4(a2x * invH, a2y * invH, a3x * invH, a3y * invH);
}

extern "C" void kernel_launch(void* const* d_in, const int* in_sizes, int n_in,
                              void* d_out, int out_size)
{
    const float* x  = (const float*)d_in[0];
    const float* wq = (const float*)d_in[1];
    const float* bq = (const float*)d_in[2];
    const float* wk = (const float*)d_in[3];
    const float* bk = (const float*)d_in[4];
    const float* wv = (const float*)d_in[5];
    const float* bv = (const float*)d_in[6];
    const float* wo = (const float*)d_in[7];
    const float* bo = (const float*)d_in[8];
    float* out = (float*)d_out;
    float* avg = out + (size_t)MROWS * EMB;

    __half *qh, *kh, *vh, *vt, *ctxh, *eg;
    float *linv;
    cudaGetSymbolAddress((void**)&qh,   g_qh);
    cudaGetSymbolAddress((void**)&kh,   g_kh);
    cudaGetSymbolAddress((void**)&vh,   g_vh);
    cudaGetSymbolAddress((void**)&vt,   g_vt);
    cudaGetSymbolAddress((void**)&ctxh, g_ctxh);
    cudaGetSymbolAddress((void**)&linv, g_linv);
    cudaGetSymbolAddress((void**)&eg,   g_e);

    const float scaling = 0.125f;   // HD^-0.5

    cudaFuncSetAttribute(attn_fused, cudaFuncAttributeMaxDynamicSharedMemorySize, FUSED_SMEM);
    cudaFuncSetAttribute(gemm_nt<0,1>, cudaFuncAttributeMaxDynamicSharedMemorySize, GEMM_SMEM);
    cudaFuncSetAttribute(gemm_nt<1,0>, cudaFuncAttributeMaxDynamicSharedMemorySize, GEMM_SMEM);

    cudaStream_t s1, s2;
    cudaStreamCreateWithFlags(&s1, cudaStreamNonBlocking);
    cudaStreamCreateWithFlags(&s2, cudaStreamNonBlocking);
    cudaEvent_t ev0, evK, evV, ev1, ev2;
    cudaEventCreateWithFlags(&ev0, cudaEventDisableTiming);
    cudaEventCreateWithFlags(&evK, cudaEventDisableTiming);
    cudaEventCreateWithFlags(&evV, cudaEventDisableTiming);
    cudaEventCreateWithFlags(&ev1, cudaEventDisableTiming);
    cudaEventCreateWithFlags(&ev2, cudaEventDisableTiming);

    dim3 gproj(EMB / 128, MROWS / 128);      // (8, 64)

    // fork: Q proj default, K proj s1, V proj + transpose s2
    cudaEventRecord(ev0, 0);
    cudaStreamWaitEvent(s1, ev0, 0);
    cudaStreamWaitEvent(s2, ev0, 0);
    gemm_nt<0,1><<<gproj, 256, GEMM_SMEM>>>(x, wq, bq, qh, MROWS, EMB, EMB, scaling);
    gemm_nt<0,1><<<gproj, 256, GEMM_SMEM, s1>>>(x, wk, bk, kh, MROWS, EMB, EMB, 1.0f);
    gemm_nt<0,1><<<gproj, 256, GEMM_SMEM, s2>>>(x, wv, bv, vh, MROWS, EMB, EMB, 1.0f);
    {
        dim3 gtr(TGT / 32, EMB / 32, BSZ);   // (64, 32, 4)
        v_transpose<<<gtr, 256, 0, s2>>>(vh, vt);
    }
    cudaEventRecord(evK, s1);
    cudaEventRecord(evV, s2);
    cudaStreamWaitEvent(0, evK, 0);
    cudaStreamWaitEvent(0, evV, 0);

    dim3 gfused(TGT / 128, BH);              // (16, 64)
    attn_fused<<<gfused, 128, FUSED_SMEM>>>(qh, kh, vt, ctxh, linv, eg);

    // fork: avg_reduce || out-projection
    cudaEventRecord(ev1, 0);
    cudaStreamWaitEvent(s1, ev1, 0);
    dim3 gavg(TGT, BSZ);                     // (2048, 4)
    avg_reduce<<<gavg, 256, 0, s1>>>(eg, linv, avg);
    cudaEventRecord(ev2, s1);

    gemm_nt<1,0><<<gproj, 256, GEMM_SMEM>>>(ctxh, wo, bo, out, MROWS, EMB, EMB, 1.0f);

    cudaStreamWaitEvent(0, ev2, 0);

    cudaEventDestroy(ev0);
    cudaEventDestroy(evK);
    cudaEventDestroy(evV);
    cudaEventDestroy(ev1);
    cudaEventDestroy(ev2);
    cudaStreamDestroy(s1);
    cudaStreamDestroy(s2);
}

// round 14
// speedup vs baseline: 1.2361x; 1.1547x over previous
#include <cuda_runtime.h>
#include <cuda_fp16.h>
#include <cstdint>
#include <math.h>

#define TGT 2048
#define BSZ 4
#define EMB 1024
#define NH  16
#define HD  64
#define MROWS (TGT * BSZ)          // 8192
#define BH (BSZ * NH)              // 64
#define SKH 72                     // padded half-stride for 64-wide fp16 tiles
#define TT ((size_t)TGT * TGT)
#define LOG2E 1.442695040888963f

// scratch (device globals: allocation-free per harness rules). uint4 for alignment.
__device__ uint4 g_xh [(size_t)MROWS * EMB / 8];     // fp16 x   [t][b][e]
__device__ uint4 g_wqh[(size_t)EMB * EMB / 8];       // fp16 weights
__device__ uint4 g_wkh[(size_t)EMB * EMB / 8];
__device__ uint4 g_wvh[(size_t)EMB * EMB / 8];
__device__ uint4 g_woh[(size_t)EMB * EMB / 8];
__device__ uint4 g_qh[(size_t)MROWS * EMB / 8];      // fp16 q   [t][b][e] (pre-scaled by 0.125*log2e)
__device__ uint4 g_kh[(size_t)MROWS * EMB / 8];      // fp16 k   [t][b][e]
__device__ uint4 g_vh[(size_t)MROWS * EMB / 8];      // fp16 v   [t][b][e]
__device__ uint4 g_vt[(size_t)MROWS * EMB / 8];      // fp16 v^T [b*EMB+e][t]
__device__ uint4 g_ctxh[(size_t)MROWS * EMB / 8];    // fp16 ctx [t][b][e]
__device__ float g_linv[(size_t)BH * TGT];           // 1/rowsum(exp S)
__device__ uint4 g_e[BH * TT / 8];                   // E=exp(S) fp16, 536 MB

// ---------------------------------------------------------------------------
// helpers
// ---------------------------------------------------------------------------
__device__ __forceinline__ unsigned f2h2(float a, float b) {
    __half2 h = __floats2half2_rn(a, b);
    return *reinterpret_cast<unsigned*>(&h);
}

__device__ __forceinline__ void mma16(float* c,
                                      unsigned a0, unsigned a1, unsigned a2, unsigned a3,
                                      unsigned b0, unsigned b1) {
    asm volatile(
        "mma.sync.aligned.m16n8k16.row.col.f32.f16.f16.f32 "
        "{%0,%1,%2,%3}, {%4,%5,%6,%7}, {%8,%9}, {%0,%1,%2,%3};\n"
        : "+f"(c[0]), "+f"(c[1]), "+f"(c[2]), "+f"(c[3])
        : "r"(a0), "r"(a1), "r"(a2), "r"(a3), "r"(b0), "r"(b1));
}

__device__ __forceinline__ void cp16(void* dst, const void* src) {
    uint32_t d = (uint32_t)__cvta_generic_to_shared(dst);
    asm volatile("cp.async.cg.shared.global [%0], [%1], 16;\n" :: "r"(d), "l"(src));
}
#define CP_COMMIT() asm volatile("cp.async.commit_group;\n" ::: "memory")
#define CP_WAIT0()  asm volatile("cp.async.wait_group 0;\n" ::: "memory")

// ---------------------------------------------------------------------------
// to_half: fp32 -> fp16 bulk convert (n4 = count/4)
// ---------------------------------------------------------------------------
__global__ __launch_bounds__(256)
void to_half(const float* __restrict__ s, __half* __restrict__ d, int n4)
{
    int i = blockIdx.x * 256 + threadIdx.x;
    if (i < n4) {
        float4 v = reinterpret_cast<const float4*>(s)[i];
        *reinterpret_cast<uint2*>(d + (size_t)i * 4) =
            make_uint2(f2h2(v.x, v.y), f2h2(v.z, v.w));
    }
}

// ---------------------------------------------------------------------------
// All-fp16 GEMM (cp.async double-buffered): C = (A @ W^T + bias) * scale
// CH: C written fp16 (else fp32). A[M,K], W[N,K] both fp16.
// BM=BN=128, BK=64. 256 threads = 8 warps (2m x 4n), warp tile 64x32.
// ---------------------------------------------------------------------------
struct GemmSmem {
    unsigned short As[2][128][SKH];
    unsigned short Bs[2][128][SKH];
};
#define GEMM_SMEM ((int)sizeof(GemmSmem))

template<int CH>
__global__ __launch_bounds__(256)
void gemm_h16(const __half* __restrict__ A, const __half* __restrict__ W,
              const float* __restrict__ bias, void* __restrict__ Cv,
              int M, int N, int K, float scale)
{
    extern __shared__ char smem_raw[];
    GemmSmem& sm = *reinterpret_cast<GemmSmem*>(smem_raw);
    int tid = threadIdx.x, lane = tid & 31, warp = tid >> 5;
    int g = lane >> 2, t = lane & 3;
    int wm = warp >> 2, wn = warp & 3;
    int m0 = blockIdx.y * 128, n0 = blockIdx.x * 128;
    const __half* Ab = A + (size_t)m0 * K;
    const __half* Wb = W + (size_t)n0 * K;
    float acc[4][4][4] = {};

    // stage k-tile 0 (pure cp.async: 128 rows x 128B per operand)
    #pragma unroll
    for (int i = 0; i < 4; i++) {
        int li = tid + i * 256;
        int r = li >> 3, c8 = li & 7;
        cp16(&sm.As[0][r][c8 * 8], Ab + (size_t)r * K + c8 * 8);
        cp16(&sm.Bs[0][r][c8 * 8], Wb + (size_t)r * K + c8 * 8);
    }
    CP_COMMIT();
    CP_WAIT0();
    __syncthreads();

    const int NKT = K / 64;   // 16
    for (int kt = 0; kt < NKT; kt++) {
        int buf = kt & 1;
        bool hasNext = (kt + 1) < NKT;
        if (hasNext) {
            int ko = (kt + 1) * 64;
            int nb = buf ^ 1;
            #pragma unroll
            for (int i = 0; i < 4; i++) {
                int li = tid + i * 256;
                int r = li >> 3, c8 = li & 7;
                cp16(&sm.As[nb][r][c8 * 8], Ab + (size_t)r * K + ko + c8 * 8);
                cp16(&sm.Bs[nb][r][c8 * 8], Wb + (size_t)r * K + ko + c8 * 8);
            }
            CP_COMMIT();
        }
        #pragma unroll
        for (int ks = 0; ks < 4; ks++) {
            int kb = ks * 16;
            unsigned a[4][4];
            #pragma unroll
            for (int am = 0; am < 4; am++) {
                int row = wm * 64 + am * 16;
                a[am][0] = *reinterpret_cast<const unsigned*>(&sm.As[buf][row + g][kb + 2 * t]);
                a[am][1] = *reinterpret_cast<const unsigned*>(&sm.As[buf][row + 8 + g][kb + 2 * t]);
                a[am][2] = *reinterpret_cast<const unsigned*>(&sm.As[buf][row + g][kb + 8 + 2 * t]);
                a[am][3] = *reinterpret_cast<const unsigned*>(&sm.As[buf][row + 8 + g][kb + 8 + 2 * t]);
            }
            unsigned b[4][2];
            #pragma unroll
            for (int an = 0; an < 4; an++) {
                int col = wn * 32 + an * 8 + g;
                b[an][0] = *reinterpret_cast<const unsigned*>(&sm.Bs[buf][col][kb + 2 * t]);
                b[an][1] = *reinterpret_cast<const unsigned*>(&sm.Bs[buf][col][kb + 8 + 2 * t]);
            }
            #pragma unroll
            for (int am = 0; am < 4; am++)
                #pragma unroll
                for (int an = 0; an < 4; an++)
                    mma16(acc[am][an], a[am][0], a[am][1], a[am][2], a[am][3],
                          b[an][0], b[an][1]);
        }
        if (hasNext) CP_WAIT0();
        __syncthreads();
    }
    #pragma unroll
    for (int am = 0; am < 4; am++) {
        int m = m0 + wm * 64 + am * 16 + g;
        #pragma unroll
        for (int an = 0; an < 4; an++) {
            int n = n0 + wn * 32 + an * 8 + 2 * t;
            float2 bv = *reinterpret_cast<const float2*>(bias + n);
            float v0 = (acc[am][an][0] + bv.x) * scale;
            float v1 = (acc[am][an][1] + bv.y) * scale;
            float v2 = (acc[am][an][2] + bv.x) * scale;
            float v3 = (acc[am][an][3] + bv.y) * scale;
            if (CH) {
                __half* Ch = (__half*)Cv;
                *reinterpret_cast<unsigned*>(Ch + (size_t)m * N + n) = f2h2(v0, v1);
                *reinterpret_cast<unsigned*>(Ch + (size_t)(m + 8) * N + n) = f2h2(v2, v3);
            } else {
                float* Cf = (float*)Cv;
                *reinterpret_cast<float2*>(Cf + (size_t)m * N + n) = make_float2(v0, v1);
                *reinterpret_cast<float2*>(Cf + (size_t)(m + 8) * N + n) = make_float2(v2, v3);
            }
        }
    }
}

// ---------------------------------------------------------------------------
// V transpose: vh [t][b][e] fp16 -> vt [(b*EMB+e)][t] fp16. 32x32 smem tiles.
// ---------------------------------------------------------------------------
__global__ __launch_bounds__(256)
void v_transpose(const __half* __restrict__ vh, __half* __restrict__ vt)
{
    __shared__ __half ts[32][33];
    int t0 = blockIdx.x * 32, e0 = blockIdx.y * 32, b = blockIdx.z;
    int tx = threadIdx.x & 31, ty = threadIdx.x >> 5;   // 32 x 8
    #pragma unroll
    for (int j = 0; j < 4; j++) {
        int r = ty * 4 + j;
        ts[r][tx] = vh[((size_t)(t0 + r) * BSZ + b) * EMB + e0 + tx];
    }
    __syncthreads();
    #pragma unroll
    for (int j = 0; j < 4; j++) {
        int r = ty * 4 + j;   // e within tile
        vt[((size_t)b * EMB + e0 + r) * TGT + t0 + tx] = ts[tx][r];
    }
}

// ---------------------------------------------------------------------------
// Fused flash attention (fp16 mma), cp.async pipelined (R13 structure).
// q is pre-scaled by 0.125*log2e, so E = exp2f(S') with no extra multiply.
// ---------------------------------------------------------------------------
struct FusedSmem {
    unsigned short Qs[128][SKH];     // Q tile; reused as E staging after hoist
    unsigned short Ks[2][64][SKH];
    unsigned short Vs[2][64][SKH];   // [dim][token]
    float lsum[128];
};
#define FUSED_SMEM ((int)sizeof(FusedSmem))

__global__ __launch_bounds__(128, 3)
void attn_fused(const __half* __restrict__ qh, const __half* __restrict__ kh,
                const __half* __restrict__ vt, __half* __restrict__ ctxh,
                float* __restrict__ linv, __half* __restrict__ eg)
{
    extern __shared__ char smem_raw[];
    FusedSmem& sm = *reinterpret_cast<FusedSmem*>(smem_raw);
    const int LDA = BSZ * EMB;
    int tid = threadIdx.x, lane = tid & 31;
    int wm = tid >> 5;
    int g = lane >> 2, t = lane & 3;
    int z = blockIdx.y;
    int b = z / NH, h = z % NH;
    int m0 = blockIdx.x * 128;
    const __half* Qb = qh + (size_t)b * EMB + h * HD;
    const __half* Kb = kh + (size_t)b * EMB + h * HD;
    const __half* Vb = vt + ((size_t)b * EMB + h * HD) * TGT;
    __half* Ez = eg + (size_t)z * TT;

    #pragma unroll
    for (int i = 0; i < 8; i++) {
        int li = tid + i * 128;
        int r = li >> 3, c8 = li & 7;
        cp16(&sm.Qs[r][c8 * 8], Qb + (size_t)(m0 + r) * LDA + c8 * 8);
    }
    #pragma unroll
    for (int i = 0; i < 4; i++) {
        int li = tid + i * 128;
        int r = li >> 3, c8 = li & 7;
        cp16(&sm.Ks[0][r][c8 * 8], Kb + (size_t)r * LDA + c8 * 8);
        cp16(&sm.Vs[0][r][c8 * 8], Vb + (size_t)r * TGT + c8 * 8);
    }
    CP_COMMIT();
    CP_WAIT0();
    __syncthreads();

    unsigned qf[2][4][4];
    #pragma unroll
    for (int am = 0; am < 2; am++) {
        int row = wm * 32 + am * 16;
        #pragma unroll
        for (int ks = 0; ks < 4; ks++) {
            int kb = ks * 16;
            qf[am][ks][0] = *reinterpret_cast<const unsigned*>(&sm.Qs[row + g][kb + 2 * t]);
            qf[am][ks][1] = *reinterpret_cast<const unsigned*>(&sm.Qs[row + 8 + g][kb + 2 * t]);
            qf[am][ks][2] = *reinterpret_cast<const unsigned*>(&sm.Qs[row + g][kb + 8 + 2 * t]);
            qf[am][ks][3] = *reinterpret_cast<const unsigned*>(&sm.Qs[row + 8 + g][kb + 8 + 2 * t]);
        }
    }

    float acc_c[2][8][4] = {};
    float lp[4] = {};

    for (int nt = 0; nt < TGT / 64; nt++) {
        int buf = nt & 1;
        bool hasNext = (nt + 1) < TGT / 64;
        if (hasNext) {
            int n1 = (nt + 1) * 64;
            int nb = buf ^ 1;
            #pragma unroll
            for (int i = 0; i < 4; i++) {
                int li = tid + i * 128;
                int r = li >> 3, c8 = li & 7;
                cp16(&sm.Ks[nb][r][c8 * 8], Kb + (size_t)(n1 + r) * LDA + c8 * 8);
                cp16(&sm.Vs[nb][r][c8 * 8], Vb + (size_t)r * TGT + n1 + c8 * 8);
            }
            CP_COMMIT();
        }

        // S' = Q' K^T  (log2e pre-folded into q)
        float acc_s[2][8][4] = {};
        #pragma unroll
        for (int ks = 0; ks < 4; ks++) {
            int kb = ks * 16;
            unsigned bb[8][2];
            #pragma unroll
            for (int an = 0; an < 8; an++) {
                int col = an * 8 + g;
                bb[an][0] = *reinterpret_cast<const unsigned*>(&sm.Ks[buf][col][kb + 2 * t]);
                bb[an][1] = *reinterpret_cast<const unsigned*>(&sm.Ks[buf][col][kb + 8 + 2 * t]);
            }
            #pragma unroll
            for (int am = 0; am < 2; am++)
                #pragma unroll
                for (int an = 0; an < 8; an++)
                    mma16(acc_s[am][an], qf[am][ks][0], qf[am][ks][1],
                          qf[am][ks][2], qf[am][ks][3], bb[an][0], bb[an][1]);
        }

        // E = exp2(S') in registers (packed as PV A-fragments)
        unsigned eh[2][16];
        #pragma unroll
        for (int am = 0; am < 2; am++) {
            #pragma unroll
            for (int an = 0; an < 8; an++) {
                float e0 = exp2f(acc_s[am][an][0]);
                float e1 = exp2f(acc_s[am][an][1]);
                float e2 = exp2f(acc_s[am][an][2]);
                float e3 = exp2f(acc_s[am][an][3]);
                lp[am * 2 + 0] += e0 + e1;
                lp[am * 2 + 1] += e2 + e3;
                eh[am][2 * an + 0] = f2h2(e0, e1);
                eh[am][2 * an + 1] = f2h2(e2, e3);
            }
        }

        // E store FIRST (STG drains while PV mma runs below)
        #pragma unroll
        for (int am = 0; am < 2; am++) {
            int r0 = wm * 32 + am * 16 + g;
            #pragma unroll
            for (int an = 0; an < 8; an++) {
                int c = an * 8 + 2 * t;
                *reinterpret_cast<unsigned*>(&sm.Qs[r0][c]) = eh[am][2 * an];
                *reinterpret_cast<unsigned*>(&sm.Qs[r0 + 8][c]) = eh[am][2 * an + 1];
            }
        }
        __syncwarp();
        {
            int n0 = nt * 64;
            int rb = wm * 32 + (lane >> 4);
            int c4 = lane & 15;
            #pragma unroll
            for (int i = 0; i < 16; i++) {
                int row = rb + i * 2;
                uint2 d = *reinterpret_cast<const uint2*>(&sm.Qs[row][c4 * 4]);
                *reinterpret_cast<uint2*>(Ez + (size_t)(m0 + row) * TGT + n0 + c4 * 4) = d;
            }
        }

        // ctx += E @ V
        #pragma unroll
        for (int ks = 0; ks < 4; ks++) {
            int kb = ks * 16;
            unsigned bb[8][2];
            #pragma unroll
            for (int an = 0; an < 8; an++) {
                int col = an * 8 + g;
                bb[an][0] = *reinterpret_cast<const unsigned*>(&sm.Vs[buf][col][kb + 2 * t]);
                bb[an][1] = *reinterpret_cast<const unsigned*>(&sm.Vs[buf][col][kb + 8 + 2 * t]);
            }
            #pragma unroll
            for (int am = 0; am < 2; am++)
                #pragma unroll
                for (int an = 0; an < 8; an++)
                    mma16(acc_c[am][an], eh[am][4 * ks + 0], eh[am][4 * ks + 1],
                          eh[am][4 * ks + 2], eh[am][4 * ks + 3],
                          bb[an][0], bb[an][1]);
        }

        if (hasNext) CP_WAIT0();
        __syncthreads();
    }

    // row sums
    #pragma unroll
    for (int r4 = 0; r4 < 4; r4++) {
        float s = lp[r4];
        s += __shfl_xor_sync(0xffffffff, s, 1);
        s += __shfl_xor_sync(0xffffffff, s, 2);
        if (t == 0)
            sm.lsum[wm * 32 + (r4 >> 1) * 16 + (r4 & 1) * 8 + g] = s;
    }
    __syncthreads();
    {
        float inv = 1.0f / sm.lsum[tid];
        linv[(size_t)z * TGT + m0 + tid] = inv;
        sm.lsum[tid] = inv;
    }
    __syncthreads();

    // normalize + write ctx (fp16)
    #pragma unroll
    for (int am = 0; am < 2; am++) {
        int rloc = wm * 32 + am * 16 + g;
        float inv0 = sm.lsum[rloc];
        float inv1 = sm.lsum[rloc + 8];
        int m = m0 + rloc;
        #pragma unroll
        for (int an = 0; an < 8; an++) {
            int n = an * 8 + 2 * t;
            __half* c0 = ctxh + ((size_t)m * BSZ + b) * EMB + h * HD + n;
            __half* c1 = ctxh + ((size_t)(m + 8) * BSZ + b) * EMB + h * HD + n;
            *reinterpret_cast<unsigned*>(c0) =
                f2h2(acc_c[am][an][0] * inv0, acc_c[am][an][1] * inv0);
            *reinterpret_cast<unsigned*>(c1) =
                f2h2(acc_c[am][an][2] * inv1, acc_c[am][an][3] * inv1);
        }
    }
}

// ---------------------------------------------------------------------------
// avg_reduce: avg[b,m,n] = (1/NH) sum_h E_h[m,n] * linv_h[m]. Memory-bound.
// ---------------------------------------------------------------------------
__global__ __launch_bounds__(256)
void avg_reduce(const __half* __restrict__ eg, const float* __restrict__ linv,
                float* __restrict__ avg)
{
    int mrow = blockIdx.x;
    int b = blockIdx.y;
    int tid = threadIdx.x;
    __shared__ float sl[NH];
    if (tid < NH) sl[tid] = linv[(size_t)(b * NH + tid) * TGT + mrow];
    __syncthreads();

    float a0x = 0.f, a0y = 0.f, a1x = 0.f, a1y = 0.f;
    float a2x = 0.f, a2y = 0.f, a3x = 0.f, a3y = 0.f;
    #pragma unroll
    for (int h = 0; h < NH; h++) {
        const float4* rowp = reinterpret_cast<const float4*>(
            eg + (size_t)(b * NH + h) * TT + (size_t)mrow * TGT);
        float4 raw = rowp[tid];
        const __half2* hp = reinterpret_cast<const __half2*>(&raw);
        float lv = sl[h];
        float2 f0 = __half22float2(hp[0]);
        float2 f1 = __half22float2(hp[1]);
        float2 f2 = __half22float2(hp[2]);
        float2 f3 = __half22float2(hp[3]);
        a0x += f0.x * lv; a0y += f0.y * lv;
        a1x += f1.x * lv; a1y += f1.y * lv;
        a2x += f2.x * lv; a2y += f2.y * lv;
        a3x += f3.x * lv; a3y += f3.y * lv;
    }
    const float invH = 1.0f / NH;
    float* op = avg + (size_t)b * TT + (size_t)mrow * TGT + tid * 8;
    *reinterpret_cast<float4*>(op) =
        make_float4(a0x * invH, a0y * invH, a1x * invH, a1y * invH);
    *reinterpret_cast<float4*>(op + 4) =
        make_float4(a2x * invH, a2y * invH, a3x * invH, a3y * invH);
}

extern "C" void kernel_launch(void* const* d_in, const int* in_sizes, int n_in,
                              void* d_out, int out_size)
{
    const float* x  = (const float*)d_in[0];
    const float* wq = (const float*)d_in[1];
    const float* bq = (const float*)d_in[2];
    const float* wk = (const float*)d_in[3];
    const float* bk = (const float*)d_in[4];
    const float* wv = (const float*)d_in[5];
    const float* bv = (const float*)d_in[6];
    const float* wo = (const float*)d_in[7];
    const float* bo = (const float*)d_in[8];
    float* out = (float*)d_out;
    float* avg = out + (size_t)MROWS * EMB;

    __half *xh, *wqh, *wkh, *wvh, *woh, *qh, *kh, *vh, *vt, *ctxh, *eg;
    float *linv;
    cudaGetSymbolAddress((void**)&xh,   g_xh);
    cudaGetSymbolAddress((void**)&wqh,  g_wqh);
    cudaGetSymbolAddress((void**)&wkh,  g_wkh);
    cudaGetSymbolAddress((void**)&wvh,  g_wvh);
    cudaGetSymbolAddress((void**)&woh,  g_woh);
    cudaGetSymbolAddress((void**)&qh,   g_qh);
    cudaGetSymbolAddress((void**)&kh,   g_kh);
    cudaGetSymbolAddress((void**)&vh,   g_vh);
    cudaGetSymbolAddress((void**)&vt,   g_vt);
    cudaGetSymbolAddress((void**)&ctxh, g_ctxh);
    cudaGetSymbolAddress((void**)&linv, g_linv);
    cudaGetSymbolAddress((void**)&eg,   g_e);

    const float qscale = 0.125f * LOG2E;   // HD^-0.5 * log2(e), exp2 in fused

    cudaFuncSetAttribute(attn_fused, cudaFuncAttributeMaxDynamicSharedMemorySize, FUSED_SMEM);
    cudaFuncSetAttribute(gemm_h16<0>, cudaFuncAttributeMaxDynamicSharedMemorySize, GEMM_SMEM);
    cudaFuncSetAttribute(gemm_h16<1>, cudaFuncAttributeMaxDynamicSharedMemorySize, GEMM_SMEM);

    cudaStream_t s1, s2;
    cudaStreamCreateWithFlags(&s1, cudaStreamNonBlocking);
    cudaStreamCreateWithFlags(&s2, cudaStreamNonBlocking);
    cudaEvent_t ev0, evK, evV, ev1, ev2;
    cudaEventCreateWithFlags(&ev0, cudaEventDisableTiming);
    cudaEventCreateWithFlags(&evK, cudaEventDisableTiming);
    cudaEventCreateWithFlags(&evV, cudaEventDisableTiming);
    cudaEventCreateWithFlags(&ev1, cudaEventDisableTiming);
    cudaEventCreateWithFlags(&ev2, cudaEventDisableTiming);

    // upfront fp16 conversions (x on 0; weights split across streams)
    const int XN4 = MROWS * EMB / 4;       // 2,097,152
    const int WN4 = EMB * EMB / 4;         // 262,144
    cudaEventRecord(ev0, 0);
    cudaStreamWaitEvent(s1, ev0, 0);
    cudaStreamWaitEvent(s2, ev0, 0);
    to_half<<<(XN4 + 255) / 256, 256>>>(x, xh, XN4);
    to_half<<<(WN4 + 255) / 256, 256>>>(wq, wqh, WN4);
    to_half<<<(WN4 + 255) / 256, 256, 0, s1>>>(wk, wkh, WN4);
    to_half<<<(WN4 + 255) / 256, 256, 0, s2>>>(wv, wvh, WN4);
    to_half<<<(WN4 + 255) / 256, 256, 0, s2>>>(wo, woh, WN4);
    // x conversion is on stream 0; K/V projections need it -> sync forks on ev after x
    cudaEvent_t evX;
    cudaEventCreateWithFlags(&evX, cudaEventDisableTiming);
    cudaEventRecord(evX, 0);
    cudaStreamWaitEvent(s1, evX, 0);
    cudaStreamWaitEvent(s2, evX, 0);

    dim3 gproj(EMB / 128, MROWS / 128);      // (8, 64)
    gemm_h16<1><<<gproj, 256, GEMM_SMEM>>>(xh, wqh, bq, qh, MROWS, EMB, EMB, qscale);
    gemm_h16<1><<<gproj, 256, GEMM_SMEM, s1>>>(xh, wkh, bk, kh, MROWS, EMB, EMB, 1.0f);
    gemm_h16<1><<<gproj, 256, GEMM_SMEM, s2>>>(xh, wvh, bv, vh, MROWS, EMB, EMB, 1.0f);
    {
        dim3 gtr(TGT / 32, EMB / 32, BSZ);   // (64, 32, 4)
        v_transpose<<<gtr, 256, 0, s2>>>(vh, vt);
    }
    cudaEventRecord(evK, s1);
    cudaEventRecord(evV, s2);
    cudaStreamWaitEvent(0, evK, 0);
    cudaStreamWaitEvent(0, evV, 0);

    dim3 gfused(TGT / 128, BH);              // (16, 64)
    attn_fused<<<gfused, 128, FUSED_SMEM>>>(qh, kh, vt, ctxh, linv, eg);

    // fork: avg_reduce || out-projection
    cudaEventRecord(ev1, 0);
    cudaStreamWaitEvent(s1, ev1, 0);
    dim3 gavg(TGT, BSZ);                     // (2048, 4)
    avg_reduce<<<gavg, 256, 0, s1>>>(eg, linv, avg);
    cudaEventRecord(ev2, s1);

    gemm_h16<0><<<gproj, 256, GEMM_SMEM>>>(ctxh, woh, bo, out, MROWS, EMB, EMB, 1.0f);

    cudaStreamWaitEvent(0, ev2, 0);

    cudaEventDestroy(ev0);
    cudaEventDestroy(evX);
    cudaEventDestroy(evK);
    cudaEventDestroy(evV);
    cudaEventDestroy(ev1);
    cudaEventDestroy(ev2);
    cudaStreamDestroy(s1);
    cudaStreamDestroy(s2);
}